// round 2
// baseline (speedup 1.0000x reference)
#include <cuda_runtime.h>
#include <cstdint>

#define T_STEPS 512
#define B_N 64
#define I_N 128
#define H_N 512
#define O_N 128
#define KLAG 32
#define NCTA 128
#define NTHR 512

// d_out layout: outputs [512,64,128] | h_last [64,512] | hc_last [32,64,512]
#define OUT_HLAST 4194304
#define OUT_HC    4227072

// ---------------- device scratch (no allocations allowed) ----------------
__device__ float g_xT[(size_t)T_STEPS * I_N * B_N];      // [t][i][b]
__device__ float g_HallT[(size_t)T_STEPS * H_N * B_N];   // [t][h][b]
__device__ float g_hbuf[2 * H_N * B_N];                  // [parity][h][b]
__device__ float g_wd[KLAG * H_N];                       // [lag][h]
__device__ unsigned g_bar;

// ---------------- helpers ----------------
union F2U { float2 f; unsigned long long u; };

__device__ __forceinline__ float2 ffma2(float2 a, float2 b, float2 c) {
    F2U ua, ub, uc, ud;
    ua.f = a; ub.f = b; uc.f = c;
    asm("fma.rn.f32x2 %0, %1, %2, %3;" : "=l"(ud.u) : "l"(ua.u), "l"(ub.u), "l"(uc.u));
    return ud.f;
}

__device__ __forceinline__ uint32_t smem_u32(const void* p) {
    return (uint32_t)__cvta_generic_to_shared(p);
}

__device__ __forceinline__ void cp16(uint32_t dst, const void* src) {
    asm volatile("cp.async.cg.shared.global [%0], [%1], 16;" :: "r"(dst), "l"(src));
}

__device__ __forceinline__ float sigf(float x) {
    return 1.0f / (1.0f + __expf(-x));
}

// ---------------- init: barrier reset, h0=0, fractional-diff weights ----------------
__global__ void init_kernel(const float* __restrict__ dv) {
    int id = blockIdx.x * blockDim.x + threadIdx.x;
    int nth = gridDim.x * blockDim.x;
    if (id == 0) g_bar = 0u;
    for (int i = id; i < 2 * H_N * B_N; i += nth) g_hbuf[i] = 0.0f;
    if (id < H_N) {
        float d = 0.5f / (1.0f + expf(-dv[id]));   // 0.5*sigmoid
        float v = 1.0f;
        for (int i = 0; i < KLAG; ++i) {
            v = v * ((float)i - d) / ((float)i + 1.0f);
            g_wd[(KLAG - 1 - i) * H_N + id] = v;   // wd[j] = v_{K-j}
        }
    }
}

// ---------------- transpose x: [t][b][i] -> [t][i][b] ----------------
__global__ void transpose_x(const float* __restrict__ x) {
    __shared__ float tile[B_N][I_N + 1];
    int t = blockIdx.x;
    const float* src = x + (size_t)t * B_N * I_N;
    for (int idx = threadIdx.x; idx < B_N * I_N; idx += blockDim.x)
        tile[idx >> 7][idx & 127] = src[idx];
    __syncthreads();
    float* dst = g_xT + (size_t)t * I_N * B_N;
    for (int idx = threadIdx.x; idx < I_N * B_N; idx += blockDim.x)
        dst[idx] = tile[idx & 63][idx >> 6];
}

// ---------------- persistent recurrence ----------------
// 128 CTAs x 512 thr. CTA owns hidden units nhb..nhb+3 for all 64 batches.
// tid = ks*64 + j*16 + bpq : ks = k-split (0..7), j = hidden (0..3), bpq -> batches 4bpq..4bpq+3
// Smem: z_s [2][128k][64b] f32 | wio4 [640][4] f4(wi,wi,wo,wo) | wc2 [640][4] f2
//       chist [32][4][32bp] f2 | wd_s [32][4] f32 | red [512][6] f2
__global__ void __launch_bounds__(NTHR, 1) recurrent_kernel(
    const float* __restrict__ W_i, const float* __restrict__ b_i,
    const float* __restrict__ W_o, const float* __restrict__ b_o,
    const float* __restrict__ W_c, const float* __restrict__ b_c,
    float* __restrict__ d_out)
{
    extern __shared__ char smem[];
    float*  z_s   = (float*) (smem);              // 65536
    float4* wio4  = (float4*)(smem + 65536);      // 40960
    float2* wc2   = (float2*)(smem + 106496);     // 20480
    float2* chist = (float2*)(smem + 126976);     // 32768
    float*  wd_s  = (float*) (smem + 159744);     // 512
    float2* red   = (float2*)(smem + 160256);     // 24576  -> total 184832

    const int tid = threadIdx.x;
    const int ks  = tid >> 6;
    const int j   = (tid >> 4) & 3;
    const int bpq = tid & 15;
    const int nhb = blockIdx.x * 4;
    const int nh  = nhb + j;

    // Stage weights once (duplicated into f32x2 lanes)
    for (int idx = tid; idx < (I_N + H_N) * 4; idx += NTHR) {
        int k = idx >> 2, jj = idx & 3;
        float wi = W_i[(size_t)k * H_N + nhb + jj];
        float wo = W_o[(size_t)k * H_N + nhb + jj];
        float wc = W_c[(size_t)k * H_N + nhb + jj];
        wio4[idx] = make_float4(wi, wi, wo, wo);
        wc2[idx]  = make_float2(wc, wc);
    }
    for (int idx = tid; idx < KLAG * 4; idx += NTHR)
        wd_s[idx] = g_wd[(idx >> 2) * H_N + nhb + (idx & 3)];
    for (int idx = tid; idx < KLAG * 4 * 32; idx += NTHR)
        chist[idx] = make_float2(0.0f, 0.0f);

    float bi = 0.f, bo = 0.f, bc = 0.f;
    if (tid < 128) { bi = b_i[nh]; bo = b_o[nh]; bc = b_c[nh]; }
    __syncthreads();

    const uint32_t zsb = smem_u32(z_s);

    // prologue: issue chunk (t=0, c=0) = x rows 0..127 into buf 0
    {
        const float* src = g_xT;
#pragma unroll
        for (int r = 0; r < 4; ++r) {
            int g = tid + r * NTHR;
            cp16(zsb + g * 16, src + g * 4);
        }
        asm volatile("cp.async.commit_group;");
    }

    for (int t = 0; t < T_STEPS; ++t) {
        float2 acc[2][3];
#pragma unroll
        for (int a = 0; a < 2; ++a)
#pragma unroll
            for (int g = 0; g < 3; ++g) acc[a][g] = make_float2(0.f, 0.f);

        for (int c = 0; c < 5; ++c) {
            __syncthreads();   // compute of chunk n-1 done -> its buffer is free
            bool last = (t == T_STEPS - 1) && (c == 4);
            if (!last) {
                int nt = (c < 4) ? t : t + 1;
                int nc = (c < 4) ? c + 1 : 0;
                const float* src = (nc == 0)
                    ? (g_xT + (size_t)nt * (I_N * B_N))
                    : (g_hbuf + (size_t)(nt & 1) * (H_N * B_N) + (size_t)(nc - 1) * (128 * B_N));
                uint32_t dstb = zsb + (uint32_t)(((t * 5 + c + 1) & 1) * 32768);
#pragma unroll
                for (int r = 0; r < 4; ++r) {
                    int g = tid + r * NTHR;
                    cp16(dstb + g * 16, src + g * 4);
                }
                asm volatile("cp.async.commit_group;");
                asm volatile("cp.async.wait_group 1;");
            } else {
                asm volatile("cp.async.wait_group 0;");
            }
            __syncthreads();   // chunk c fully in smem for all threads

            const float4* zv  = (const float4*)(z_s + (((t * 5 + c) & 1) ? 8192 : 0))
                                + ks * 256 + bpq;                 // row = 16 float4
            const float4* wv  = wio4 + (size_t)(c * 128 + ks * 16) * 4 + j;
            const float2* wcv = wc2  + (size_t)(c * 128 + ks * 16) * 4 + j;
#pragma unroll 4
            for (int kk = 0; kk < 16; ++kk) {
                float4 z4 = zv[kk * 16];
                float4 w4 = wv[kk * 4];
                float2 wcc = wcv[kk * 4];
                float2 za  = make_float2(z4.x, z4.y);
                float2 zb2 = make_float2(z4.z, z4.w);
                float2 wi2 = make_float2(w4.x, w4.y);
                float2 wo2 = make_float2(w4.z, w4.w);
                acc[0][0] = ffma2(za,  wi2, acc[0][0]);
                acc[1][0] = ffma2(zb2, wi2, acc[1][0]);
                acc[0][1] = ffma2(za,  wo2, acc[0][1]);
                acc[1][1] = ffma2(zb2, wo2, acc[1][1]);
                acc[0][2] = ffma2(za,  wcc, acc[0][2]);
                acc[1][2] = ffma2(zb2, wcc, acc[1][2]);
            }
        }

        __syncthreads();   // all computes done; red free
#pragma unroll
        for (int a = 0; a < 2; ++a)
#pragma unroll
            for (int g = 0; g < 3; ++g)
                red[tid * 6 + a * 3 + g] = acc[a][g];
        __syncthreads();

        if (tid < 128) {   // ks in {0,1}: handles bpair bp = 2*bpq + ks
            const int bp = 2 * bpq + ks;
            float2 pi = make_float2(bi, bi);
            float2 po = make_float2(bo, bo);
            float2 pc = make_float2(bc, bc);
#pragma unroll
            for (int w = 0; w < 8; ++w) {
                const float2* r = &red[(size_t)(w * 64 + j * 16 + bpq) * 6 + ks * 3];
                pi.x += r[0].x; pi.y += r[0].y;
                po.x += r[1].x; po.y += r[1].y;
                pc.x += r[2].x; pc.y += r[2].y;
            }
            float2 ig, og, gg;
            ig.x = sigf(pi.x); ig.y = sigf(pi.y);
            og.x = sigf(po.x); og.y = sigf(po.y);
            gg.x = tanhf(pc.x); gg.y = tanhf(pc.y);

            float2 frac = make_float2(0.f, 0.f);
#pragma unroll
            for (int l = 0; l < KLAG; ++l) {
                float w = wd_s[l * 4 + j];
                float2 ch = chist[(size_t)(((t + l) & 31) * 4 + j) * 32 + bp];
                frac = ffma2(ch, make_float2(w, w), frac);
            }
            float2 c2;
            c2.x = ig.x * gg.x - frac.x;
            c2.y = ig.y * gg.y - frac.y;
            chist[(size_t)((t & 31) * 4 + j) * 32 + bp] = c2;

            float2 h2;
            h2.x = og.x * tanhf(c2.x);
            h2.y = og.y * tanhf(c2.y);

            int par = (t + 1) & 1;
            *(float2*)&g_hbuf[(size_t)par * H_N * B_N + nh * B_N + 2 * bp] = h2;
            *(float2*)&g_HallT[(size_t)t * H_N * B_N + nh * B_N + 2 * bp] = h2;
            if (t == T_STEPS - 1) {
                d_out[OUT_HLAST + (size_t)(2 * bp) * H_N + nh]     = h2.x;
                d_out[OUT_HLAST + (size_t)(2 * bp + 1) * H_N + nh] = h2.y;
            }
        }
        __syncthreads();

        // grid barrier (monotonic counter)
        if (tid == 0) {
            __threadfence();
            atomicAdd(&g_bar, 1u);
            unsigned target = (unsigned)(t + 1) * NCTA;
            while (*((volatile unsigned*)&g_bar) < target) { }
            __threadfence();
        }
        __syncthreads();
    }

    // dump hc_last: slot l == lag l (512 % 32 == 0)
    const float* chf = (const float*)chist;
    for (int idx = tid; idx < KLAG * B_N * 4; idx += NTHR) {
        int l = idx >> 8;
        int rem = idx & 255;
        int b = rem >> 2;
        int jj = rem & 3;
        float v = chf[((size_t)(l * 4 + jj) * 32 + (b >> 1)) * 2 + (b & 1)];
        d_out[OUT_HC + (size_t)l * (B_N * H_N) + (size_t)b * H_N + nhb + jj] = v;
    }
}

// ---------------- output projection: out[t,b,:] = Hall[t,b,:] @ W_out + b_out ----------------
__global__ void __launch_bounds__(256) proj_kernel(
    const float* __restrict__ W_out, const float* __restrict__ b_out,
    float* __restrict__ out)
{
    __shared__ float At[32 * 64];    // [k][b]
    __shared__ float Wt[32 * 128];   // [k][o]
    int t = blockIdx.x;
    int tid = threadIdx.x;
    int tx = tid & 15, ty = tid >> 4;

    float2 acc[4][4];
#pragma unroll
    for (int a = 0; a < 4; ++a)
#pragma unroll
        for (int p = 0; p < 4; ++p) acc[a][p] = make_float2(0.f, 0.f);

    const float* Asrc = g_HallT + (size_t)t * H_N * B_N;
    for (int c = 0; c < 16; ++c) {
        __syncthreads();
        {
            float4* At4 = (float4*)At;
            const float4* s4 = (const float4*)(Asrc + (size_t)c * 2048);
            for (int i = tid; i < 512; i += 256) At4[i] = s4[i];
            float4* Wt4 = (float4*)Wt;
            const float4* w4 = (const float4*)(W_out + (size_t)c * 32 * 128);
            for (int i = tid; i < 1024; i += 256) Wt4[i] = w4[i];
        }
        __syncthreads();
        const float4* av = (const float4*)At + ty;
        const float2* wv = (const float2*)Wt + tx;
#pragma unroll 4
        for (int k = 0; k < 32; ++k) {
            float4 a4 = av[k * 16];
            float2 w[4];
#pragma unroll
            for (int p = 0; p < 4; ++p) w[p] = wv[k * 64 + p * 16];
            float2 ad[4];
            ad[0] = make_float2(a4.x, a4.x);
            ad[1] = make_float2(a4.y, a4.y);
            ad[2] = make_float2(a4.z, a4.z);
            ad[3] = make_float2(a4.w, a4.w);
#pragma unroll
            for (int a = 0; a < 4; ++a)
#pragma unroll
                for (int p = 0; p < 4; ++p)
                    acc[a][p] = ffma2(w[p], ad[a], acc[a][p]);
        }
    }

    float* orow = out + (size_t)t * B_N * O_N;
#pragma unroll
    for (int a = 0; a < 4; ++a) {
        int b = ty * 4 + a;
#pragma unroll
        for (int p = 0; p < 4; ++p) {
            int op = tx + p * 16;
            float2 bo = *(const float2*)(b_out + 2 * op);
            float2 r = make_float2(acc[a][p].x + bo.x, acc[a][p].y + bo.y);
            *(float2*)(orow + (size_t)b * O_N + 2 * op) = r;
        }
    }
}

// ---------------- launch ----------------
extern "C" void kernel_launch(void* const* d_in, const int* in_sizes, int n_in,
                              void* d_out, int out_size)
{
    (void)in_sizes; (void)n_in; (void)out_size;
    const float* x     = (const float*)d_in[0];
    const float* W_i   = (const float*)d_in[1];
    const float* b_i   = (const float*)d_in[2];
    const float* W_o   = (const float*)d_in[3];
    const float* b_o   = (const float*)d_in[4];
    const float* W_c   = (const float*)d_in[5];
    const float* b_c   = (const float*)d_in[6];
    const float* W_out = (const float*)d_in[7];
    const float* b_out = (const float*)d_in[8];
    const float* dv    = (const float*)d_in[9];
    float* out = (float*)d_out;

    cudaFuncSetAttribute(recurrent_kernel,
                         cudaFuncAttributeMaxDynamicSharedMemorySize, 184832);

    init_kernel<<<64, 512>>>(dv);
    transpose_x<<<T_STEPS, 256>>>(x);
    recurrent_kernel<<<NCTA, NTHR, 184832>>>(W_i, b_i, W_o, b_o, W_c, b_c, out);
    proj_kernel<<<T_STEPS, 256>>>(W_out, b_out, out);
}

// round 3
// speedup vs baseline: 1.0431x; 1.0431x over previous
#include <cuda_runtime.h>
#include <cstdint>

#define T_STEPS 512
#define B_N 64
#define I_N 128
#define H_N 512
#define O_N 128
#define KLAG 32
#define NCTA 128
#define NTHR 512

// d_out layout: outputs [512,64,128] | h_last [64,512] | hc_last [32,64,512]
#define OUT_HLAST 4194304
#define OUT_HC    4227072

#define SMEM_TOTAL 221696

// ---------------- device scratch (no allocations allowed) ----------------
__device__ float g_xT[(size_t)T_STEPS * I_N * B_N];      // [t][i][b]
__device__ float g_HallT[(size_t)T_STEPS * H_N * B_N];   // [t][h][b]
__device__ float g_zero[H_N * B_N];                      // stays 0 (never written)
__device__ float g_wd[KLAG * H_N];                       // [lag][h]
__device__ unsigned g_flags[NCTA * 32];                  // 128B-strided arrival flags

// ---------------- helpers ----------------
union F2U { float2 f; unsigned long long u; };

__device__ __forceinline__ float2 ffma2(float2 a, float2 b, float2 c) {
    F2U ua, ub, uc, ud;
    ua.f = a; ub.f = b; uc.f = c;
    asm("fma.rn.f32x2 %0, %1, %2, %3;" : "=l"(ud.u) : "l"(ua.u), "l"(ub.u), "l"(uc.u));
    return ud.f;
}

__device__ __forceinline__ uint32_t smem_u32(const void* p) {
    return (uint32_t)__cvta_generic_to_shared(p);
}

__device__ __forceinline__ void cp16(uint32_t dst, const void* src) {
    asm volatile("cp.async.cg.shared.global [%0], [%1], 16;" :: "r"(dst), "l"(src));
}

__device__ __forceinline__ float sigf(float x) {
    return 1.0f / (1.0f + __expf(-x));
}
// exact identity tanh; only __expf rounding enters (~1e-7)
__device__ __forceinline__ float tanh_f(float x) {
    float e = __expf(2.0f * x);
    return 1.0f - __fdividef(2.0f, e + 1.0f);
}

__device__ __forceinline__ void flag_store(unsigned* p, unsigned v) {
    asm volatile("st.release.gpu.global.u32 [%0], %1;" :: "l"(p), "r"(v) : "memory");
}
__device__ __forceinline__ unsigned flag_load(const unsigned* p) {
    unsigned v;
    asm volatile("ld.acquire.gpu.global.u32 %0, [%1];" : "=r"(v) : "l"(p) : "memory");
    return v;
}

// ---------------- init: flags reset + fractional-diff weights ----------------
__global__ void init_kernel(const float* __restrict__ dv) {
    int id = blockIdx.x * blockDim.x + threadIdx.x;
    if (id < NCTA * 32) g_flags[id] = 0u;
    if (id < H_N) {
        float d = 0.5f / (1.0f + expf(-dv[id]));   // 0.5*sigmoid
        float v = 1.0f;
        for (int i = 0; i < KLAG; ++i) {
            v = v * ((float)i - d) / ((float)i + 1.0f);
            g_wd[(KLAG - 1 - i) * H_N + id] = v;   // wd[j] = v_{K-j}
        }
    }
}

// ---------------- transpose x: [t][b][i] -> [t][i][b] ----------------
__global__ void transpose_x(const float* __restrict__ x) {
    __shared__ float tile[B_N][I_N + 1];
    int t = blockIdx.x;
    const float* src = x + (size_t)t * B_N * I_N;
    for (int idx = threadIdx.x; idx < B_N * I_N; idx += blockDim.x)
        tile[idx >> 7][idx & 127] = src[idx];
    __syncthreads();
    float* dst = g_xT + (size_t)t * I_N * B_N;
    for (int idx = threadIdx.x; idx < I_N * B_N; idx += blockDim.x)
        dst[idx] = tile[idx & 63][idx >> 6];
}

// ---------------- persistent recurrence ----------------
// 128 CTAs x 512 thr. CTA owns hidden units nhb..nhb+3 for all 64 batches.
// tid = ks*64 + j*16 + bpq
// Smem: z_s [3][128k][64b] | wio4 [640][4] f4 | wc2 [640][4] f2
//       chist [32][4][32bp] f2 | wd_s [32][4] | red [512][7] f2 (6 used + pad)
__global__ void __launch_bounds__(NTHR, 1) recurrent_kernel(
    const float* __restrict__ W_i, const float* __restrict__ b_i,
    const float* __restrict__ W_o, const float* __restrict__ b_o,
    const float* __restrict__ W_c, const float* __restrict__ b_c,
    float* __restrict__ d_out)
{
    extern __shared__ char smem[];
    float*  z_s   = (float*) (smem);               // 98304 (3 x 32KB)
    float4* wio4  = (float4*)(smem + 98304);       // 40960
    float2* wc2   = (float2*)(smem + 139264);      // 20480
    float2* chist = (float2*)(smem + 159744);      // 32768
    float*  wd_s  = (float*) (smem + 192512);      // 512
    float2* red   = (float2*)(smem + 193024);      // 28672 -> 221696

    const int tid = threadIdx.x;
    const int ks  = tid >> 6;
    const int j   = (tid >> 4) & 3;
    const int bpq = tid & 15;
    const int nhb = blockIdx.x * 4;
    const int nh  = nhb + j;

    // Stage weights once (duplicated into f32x2 lanes)
    for (int idx = tid; idx < (I_N + H_N) * 4; idx += NTHR) {
        int k = idx >> 2, jj = idx & 3;
        float wi = W_i[(size_t)k * H_N + nhb + jj];
        float wo = W_o[(size_t)k * H_N + nhb + jj];
        float wc = W_c[(size_t)k * H_N + nhb + jj];
        wio4[idx] = make_float4(wi, wi, wo, wo);
        wc2[idx]  = make_float2(wc, wc);
    }
    for (int idx = tid; idx < KLAG * 4; idx += NTHR)
        wd_s[idx] = g_wd[(idx >> 2) * H_N + nhb + (idx & 3)];
    for (int idx = tid; idx < KLAG * 4 * 32; idx += NTHR)
        chist[idx] = make_float2(0.0f, 0.0f);

    float bi = 0.f, bo = 0.f, bc = 0.f;
    if (tid < 128) { bi = b_i[nh]; bo = b_o[nh]; bc = b_c[nh]; }
    __syncthreads();

    const uint32_t zsb = smem_u32(z_s);

    // prologue: chunk u=0 (x, t=0) into buf 0
    {
#pragma unroll
        for (int r = 0; r < 4; ++r) {
            int g = tid + r * NTHR;
            cp16(zsb + g * 16, g_xT + g * 4);
        }
        asm volatile("cp.async.commit_group;");
    }

    for (int t = 0; t < T_STEPS; ++t) {
        float2 acc[2][3];
#pragma unroll
        for (int a = 0; a < 2; ++a)
#pragma unroll
            for (int g = 0; g < 3; ++g) acc[a][g] = make_float2(0.f, 0.f);

        for (int c = 0; c < 5; ++c) {
            const int u = t * 5 + c;
            bool last = (t == T_STEPS - 1) && (c == 4);
            if (!last) {
                int nt, nc;
                if (c < 4) { nt = t; nc = c + 1; } else { nt = t + 1; nc = 0; }
                const float* src;
                if (nc == 0) {
                    src = g_xT + (size_t)nt * 8192;
                } else {
                    const float* hb = (nt == 0) ? g_zero
                                                : (g_HallT + (size_t)(nt - 1) * 32768);
                    src = hb + (size_t)(nc - 1) * 8192;
                }
                uint32_t dstb = zsb + (uint32_t)(((u + 1) % 3) * 32768);
#pragma unroll
                for (int r = 0; r < 4; ++r) {
                    int g = tid + r * NTHR;
                    cp16(dstb + g * 16, src + g * 4);
                }
                asm volatile("cp.async.commit_group;");
                asm volatile("cp.async.wait_group 1;");
            } else {
                asm volatile("cp.async.wait_group 0;");
            }
            __syncthreads();   // chunk u resident for all threads; buf (u+1)%3 free

            const float4* zv  = (const float4*)(z_s + (u % 3) * 8192) + ks * 256 + bpq;
            const float4* wv  = wio4 + (size_t)(c * 128 + ks * 16) * 4 + j;
            const float2* wcv = wc2  + (size_t)(c * 128 + ks * 16) * 4 + j;
#pragma unroll 4
            for (int kk = 0; kk < 16; ++kk) {
                float4 z4 = zv[kk * 16];
                float4 w4 = wv[kk * 4];
                float2 wcc = wcv[kk * 4];
                float2 za  = make_float2(z4.x, z4.y);
                float2 zb2 = make_float2(z4.z, z4.w);
                float2 wi2 = make_float2(w4.x, w4.y);
                float2 wo2 = make_float2(w4.z, w4.w);
                acc[0][0] = ffma2(za,  wi2, acc[0][0]);
                acc[1][0] = ffma2(zb2, wi2, acc[1][0]);
                acc[0][1] = ffma2(za,  wo2, acc[0][1]);
                acc[1][1] = ffma2(zb2, wo2, acc[1][1]);
                acc[0][2] = ffma2(za,  wcc, acc[0][2]);
                acc[1][2] = ffma2(zb2, wcc, acc[1][2]);
            }
        }

        // k-split reduction (own slot, no pre-sync needed: prior readers
        // finished before the previous grid barrier)
#pragma unroll
        for (int a = 0; a < 2; ++a)
#pragma unroll
            for (int g = 0; g < 3; ++g)
                red[tid * 7 + a * 3 + g] = acc[a][g];
        __syncthreads();

        if (tid < 128) {   // handles b-pair bp = 2*bpq + ks
            const int bp = 2 * bpq + ks;
            float2 pi = make_float2(bi, bi);
            float2 po = make_float2(bo, bo);
            float2 pc = make_float2(bc, bc);
#pragma unroll
            for (int w = 0; w < 8; ++w) {
                const float2* r = &red[(size_t)(w * 64 + j * 16 + bpq) * 7 + ks * 3];
                pi.x += r[0].x; pi.y += r[0].y;
                po.x += r[1].x; po.y += r[1].y;
                pc.x += r[2].x; pc.y += r[2].y;
            }

            // fractional memory (4-way ILP)
            float2 f0 = make_float2(0.f, 0.f), f1 = f0, f2 = f0, f3 = f0;
#pragma unroll
            for (int l = 0; l < KLAG; l += 4) {
                float2 w0 = make_float2(wd_s[(l    ) * 4 + j], 0.f); w0.y = w0.x;
                float2 w1 = make_float2(wd_s[(l + 1) * 4 + j], 0.f); w1.y = w1.x;
                float2 w2 = make_float2(wd_s[(l + 2) * 4 + j], 0.f); w2.y = w2.x;
                float2 w3 = make_float2(wd_s[(l + 3) * 4 + j], 0.f); w3.y = w3.x;
                f0 = ffma2(chist[(size_t)(((t + l    ) & 31) * 4 + j) * 32 + bp], w0, f0);
                f1 = ffma2(chist[(size_t)(((t + l + 1) & 31) * 4 + j) * 32 + bp], w1, f1);
                f2 = ffma2(chist[(size_t)(((t + l + 2) & 31) * 4 + j) * 32 + bp], w2, f2);
                f3 = ffma2(chist[(size_t)(((t + l + 3) & 31) * 4 + j) * 32 + bp], w3, f3);
            }
            float2 frac;
            frac.x = (f0.x + f1.x) + (f2.x + f3.x);
            frac.y = (f0.y + f1.y) + (f2.y + f3.y);

            float2 ig, og, gg;
            ig.x = sigf(pi.x);   ig.y = sigf(pi.y);
            og.x = sigf(po.x);   og.y = sigf(po.y);
            gg.x = tanh_f(pc.x); gg.y = tanh_f(pc.y);

            float2 c2;
            c2.x = ig.x * gg.x - frac.x;
            c2.y = ig.y * gg.y - frac.y;
            chist[(size_t)((t & 31) * 4 + j) * 32 + bp] = c2;

            float2 h2;
            h2.x = og.x * tanh_f(c2.x);
            h2.y = og.y * tanh_f(c2.y);

            *(float2*)&g_HallT[(size_t)t * 32768 + (size_t)nh * B_N + 2 * bp] = h2;
            if (t == T_STEPS - 1) {
                d_out[OUT_HLAST + (size_t)(2 * bp) * H_N + nh]     = h2.x;
                d_out[OUT_HLAST + (size_t)(2 * bp + 1) * H_N + nh] = h2.y;
            }
        }
        __syncthreads();

        // grid barrier: per-CTA release flags, 128 parallel acquire-pollers
        if (t < T_STEPS - 1) {
            unsigned target = (unsigned)(t + 1);
            if (tid == 0) flag_store(&g_flags[blockIdx.x * 32], target);
            if (tid < 128) {
                while (flag_load(&g_flags[tid * 32]) < target) { }
            }
            __syncthreads();
        }
    }

    // dump hc_last: slot l == lag l (512 % 32 == 0)
    const float* chf = (const float*)chist;
    for (int idx = tid; idx < KLAG * B_N * 4; idx += NTHR) {
        int l = idx >> 8;
        int rem = idx & 255;
        int b = rem >> 2;
        int jj = rem & 3;
        float v = chf[((size_t)(l * 4 + jj) * 32 + (b >> 1)) * 2 + (b & 1)];
        d_out[OUT_HC + (size_t)l * (B_N * H_N) + (size_t)b * H_N + nhb + jj] = v;
    }
}

// ---------------- output projection: out[t,b,:] = Hall[t,b,:] @ W_out + b_out ----------------
__global__ void __launch_bounds__(256) proj_kernel(
    const float* __restrict__ W_out, const float* __restrict__ b_out,
    float* __restrict__ out)
{
    __shared__ float At[32 * 64];    // [k][b]
    __shared__ float Wt[32 * 128];   // [k][o]
    int t = blockIdx.x;
    int tid = threadIdx.x;
    int tx = tid & 15, ty = tid >> 4;

    float2 acc[4][4];
#pragma unroll
    for (int a = 0; a < 4; ++a)
#pragma unroll
        for (int p = 0; p < 4; ++p) acc[a][p] = make_float2(0.f, 0.f);

    const float* Asrc = g_HallT + (size_t)t * H_N * B_N;
    for (int c = 0; c < 16; ++c) {
        __syncthreads();
        {
            float4* At4 = (float4*)At;
            const float4* s4 = (const float4*)(Asrc + (size_t)c * 2048);
            for (int i = tid; i < 512; i += 256) At4[i] = s4[i];
            float4* Wt4 = (float4*)Wt;
            const float4* w4 = (const float4*)(W_out + (size_t)c * 32 * 128);
            for (int i = tid; i < 1024; i += 256) Wt4[i] = w4[i];
        }
        __syncthreads();
        const float4* av = (const float4*)At + ty;
        const float2* wv = (const float2*)Wt + tx;
#pragma unroll 4
        for (int k = 0; k < 32; ++k) {
            float4 a4 = av[k * 16];
            float2 w[4];
#pragma unroll
            for (int p = 0; p < 4; ++p) w[p] = wv[k * 64 + p * 16];
            float2 ad[4];
            ad[0] = make_float2(a4.x, a4.x);
            ad[1] = make_float2(a4.y, a4.y);
            ad[2] = make_float2(a4.z, a4.z);
            ad[3] = make_float2(a4.w, a4.w);
#pragma unroll
            for (int a = 0; a < 4; ++a)
#pragma unroll
                for (int p = 0; p < 4; ++p)
                    acc[a][p] = ffma2(w[p], ad[a], acc[a][p]);
        }
    }

    float* orow = out + (size_t)t * B_N * O_N;
#pragma unroll
    for (int a = 0; a < 4; ++a) {
        int b = ty * 4 + a;
#pragma unroll
        for (int p = 0; p < 4; ++p) {
            int op = tx + p * 16;
            float2 bo = *(const float2*)(b_out + 2 * op);
            float2 r = make_float2(acc[a][p].x + bo.x, acc[a][p].y + bo.y);
            *(float2*)(orow + (size_t)b * O_N + 2 * op) = r;
        }
    }
}

// ---------------- launch ----------------
extern "C" void kernel_launch(void* const* d_in, const int* in_sizes, int n_in,
                              void* d_out, int out_size)
{
    (void)in_sizes; (void)n_in; (void)out_size;
    const float* x     = (const float*)d_in[0];
    const float* W_i   = (const float*)d_in[1];
    const float* b_i   = (const float*)d_in[2];
    const float* W_o   = (const float*)d_in[3];
    const float* b_o   = (const float*)d_in[4];
    const float* W_c   = (const float*)d_in[5];
    const float* b_c   = (const float*)d_in[6];
    const float* W_out = (const float*)d_in[7];
    const float* b_out = (const float*)d_in[8];
    const float* dv    = (const float*)d_in[9];
    float* out = (float*)d_out;

    cudaFuncSetAttribute(recurrent_kernel,
                         cudaFuncAttributeMaxDynamicSharedMemorySize, SMEM_TOTAL);

    init_kernel<<<16, 512>>>(dv);
    transpose_x<<<T_STEPS, 256>>>(x);
    recurrent_kernel<<<NCTA, NTHR, SMEM_TOTAL>>>(W_i, b_i, W_o, b_o, W_c, b_c, out);
    proj_kernel<<<T_STEPS, 256>>>(W_out, b_out, out);
}

// round 4
// speedup vs baseline: 1.0913x; 1.0462x over previous
#include <cuda_runtime.h>
#include <cstdint>

#define T_STEPS 512
#define B_N 64
#define I_N 128
#define H_N 512
#define O_N 128
#define KLAG 32
#define NCTA 128
#define NTHR 512

// d_out layout: outputs [512,64,128] | h_last [64,512] | hc_last [32,64,512]
#define OUT_HLAST 4194304
#define OUT_HC    4227072

// smem byte offsets
#define OFF_XBUF 0u
#define OFF_HB   32768u          // 3 x 32KB ring
#define OFF_RED  32768u          // aliases HB0/HB1 (53248B, lifetime-disjoint)
#define OFF_WIO  131072u         // [640][4] float4 (wi,wi,wo,wo)
#define OFF_WC2  172032u         // [640][4] float2 (wc,wc)
#define OFF_CH   192512u         // chist [32][4][32] float2
#define OFF_WD   225280u         // wd [32][4] float
#define SMEM_TOTAL 225792

// ---------------- device scratch ----------------
__device__ float g_xT[(size_t)T_STEPS * I_N * B_N];      // [t][i][b]
__device__ float g_HallT[(size_t)T_STEPS * H_N * B_N];   // [t][h][b]
__device__ float g_zero[H_N * B_N];                      // never written
__device__ float g_wd[KLAG * H_N];
__device__ unsigned g_flags[NCTA * 32];

// ---------------- helpers ----------------
union F2U { float2 f; unsigned long long u; };

__device__ __forceinline__ float2 ffma2(float2 a, float2 b, float2 c) {
    F2U ua, ub, uc, ud;
    ua.f = a; ub.f = b; uc.f = c;
    asm("fma.rn.f32x2 %0, %1, %2, %3;" : "=l"(ud.u) : "l"(ua.u), "l"(ub.u), "l"(uc.u));
    return ud.f;
}
__device__ __forceinline__ uint32_t smem_u32(const void* p) {
    return (uint32_t)__cvta_generic_to_shared(p);
}
__device__ __forceinline__ void cp16(uint32_t dst, const void* src) {
    asm volatile("cp.async.cg.shared.global [%0], [%1], 16;" :: "r"(dst), "l"(src));
}
#define CP_COMMIT() asm volatile("cp.async.commit_group;")
#define CP_WAIT(n)  asm volatile("cp.async.wait_group %0;" :: "n"(n))

__device__ __forceinline__ float sigf(float x) { return 1.0f / (1.0f + __expf(-x)); }
__device__ __forceinline__ float tanh_f(float x) {
    float e = __expf(2.0f * x);
    return 1.0f - __fdividef(2.0f, e + 1.0f);
}
__device__ __forceinline__ void flag_store(unsigned* p, unsigned v) {
    asm volatile("st.release.gpu.global.u32 [%0], %1;" :: "l"(p), "r"(v) : "memory");
}
__device__ __forceinline__ unsigned flag_load(const unsigned* p) {
    unsigned v;
    asm volatile("ld.acquire.gpu.global.u32 %0, [%1];" : "=r"(v) : "l"(p) : "memory");
    return v;
}

// ---------------- init ----------------
__global__ void init_kernel(const float* __restrict__ dv) {
    int id = blockIdx.x * blockDim.x + threadIdx.x;
    if (id < NCTA * 32) g_flags[id] = 0u;
    if (id < H_N) {
        float d = 0.5f / (1.0f + expf(-dv[id]));
        float v = 1.0f;
        for (int i = 0; i < KLAG; ++i) {
            v = v * ((float)i - d) / ((float)i + 1.0f);
            g_wd[(KLAG - 1 - i) * H_N + id] = v;
        }
    }
}

// ---------------- transpose x: [t][b][i] -> [t][i][b] ----------------
__global__ void transpose_x(const float* __restrict__ x) {
    __shared__ float tile[B_N][I_N + 1];
    int t = blockIdx.x;
    const float* src = x + (size_t)t * B_N * I_N;
    for (int idx = threadIdx.x; idx < B_N * I_N; idx += blockDim.x)
        tile[idx >> 7][idx & 127] = src[idx];
    __syncthreads();
    float* dst = g_xT + (size_t)t * I_N * B_N;
    for (int idx = threadIdx.x; idx < I_N * B_N; idx += blockDim.x)
        dst[idx] = tile[idx & 63][idx >> 6];
}

// ---------------- persistent recurrence ----------------
// tid = ks*32 + j*8 + bq ; ks=0..15 k-split, j=0..3 hidden, bq=0..7.
// Thread covers batches {4bq..4bq+3} U {32+4bq..32+4bq+3} = pairs
// p0=2bq, p1=2bq+1, p2=16+2bq, p3=17+2bq, 8 k per chunk (klocal ks*8..+8).
struct Acc { float2 a[3][4]; };

__device__ __forceinline__ void acc_zero(Acc& A) {
#pragma unroll
    for (int g = 0; g < 3; ++g)
#pragma unroll
        for (int p = 0; p < 4; ++p) A.a[g][p] = make_float2(0.f, 0.f);
}

__device__ __forceinline__ void gemm_part(
    const float4* __restrict__ z4, const float4* __restrict__ wv,
    const float2* __restrict__ wcv, Acc& A, int kk0, int kk1)
{
#pragma unroll 4
    for (int kk = kk0; kk < kk1; ++kk) {
        float4 Z0 = z4[kk * 16];
        float4 Z1 = z4[kk * 16 + 8];
        float4 w4 = wv[kk * 4];
        float2 wc = wcv[kk * 4];
        float2 wi = make_float2(w4.x, w4.y);
        float2 wo = make_float2(w4.z, w4.w);
        float2 a0 = make_float2(Z0.x, Z0.y), a1 = make_float2(Z0.z, Z0.w);
        float2 a2 = make_float2(Z1.x, Z1.y), a3 = make_float2(Z1.z, Z1.w);
        A.a[0][0] = ffma2(a0, wi, A.a[0][0]);
        A.a[0][1] = ffma2(a1, wi, A.a[0][1]);
        A.a[0][2] = ffma2(a2, wi, A.a[0][2]);
        A.a[0][3] = ffma2(a3, wi, A.a[0][3]);
        A.a[1][0] = ffma2(a0, wo, A.a[1][0]);
        A.a[1][1] = ffma2(a1, wo, A.a[1][1]);
        A.a[1][2] = ffma2(a2, wo, A.a[1][2]);
        A.a[1][3] = ffma2(a3, wo, A.a[1][3]);
        A.a[2][0] = ffma2(a0, wc, A.a[2][0]);
        A.a[2][1] = ffma2(a1, wc, A.a[2][1]);
        A.a[2][2] = ffma2(a2, wc, A.a[2][2]);
        A.a[2][3] = ffma2(a3, wc, A.a[2][3]);
    }
}

__device__ __forceinline__ void commit_chunk(uint32_t dst, const float* __restrict__ src, int tid) {
#pragma unroll
    for (int r = 0; r < 4; ++r) {
        int g = tid + r * NTHR;
        cp16(dst + (uint32_t)g * 16u, src + (size_t)g * 4);
    }
    CP_COMMIT();
}

__global__ void __launch_bounds__(NTHR, 1) recurrent_kernel(
    const float* __restrict__ W_i, const float* __restrict__ b_i,
    const float* __restrict__ W_o, const float* __restrict__ b_o,
    const float* __restrict__ W_c, const float* __restrict__ b_c,
    float* __restrict__ d_out)
{
    extern __shared__ char smem[];
    const int tid = threadIdx.x;
    const int ks  = tid >> 5;
    const int j   = (tid >> 3) & 3;
    const int bq  = tid & 7;
    const int nhb = blockIdx.x * 4;

    float4* wio = (float4*)(smem + OFF_WIO);
    float2* wcc = (float2*)(smem + OFF_WC2);
    float2* ch  = (float2*)(smem + OFF_CH);
    float*  wds = (float*) (smem + OFF_WD);
    float2* red = (float2*)(smem + OFF_RED);

    // Stage weights once
    for (int idx = tid; idx < (I_N + H_N) * 4; idx += NTHR) {
        int kg = idx >> 2, jj = idx & 3;
        float wi = W_i[(size_t)kg * H_N + nhb + jj];
        float wo = W_o[(size_t)kg * H_N + nhb + jj];
        float wc = W_c[(size_t)kg * H_N + nhb + jj];
        wio[idx] = make_float4(wi, wi, wo, wo);
        wcc[idx] = make_float2(wc, wc);
    }
    for (int idx = tid; idx < KLAG * 4; idx += NTHR)
        wds[idx] = g_wd[(idx >> 2) * H_N + nhb + (idx & 3)];
    for (int idx = tid; idx < KLAG * 4 * 32; idx += NTHR)
        ch[idx] = make_float2(0.f, 0.f);

    float bi = 0.f, bo = 0.f, bc = 0.f;
    if (tid < 128) {
        int nh = nhb + (tid >> 5);
        bi = b_i[nh]; bo = b_o[nh]; bc = b_c[nh];
    }
    __syncthreads();

    const uint32_t sb = smem_u32(smem);
    const uint32_t XB = sb + OFF_XBUF;
    const uint32_t HB0 = sb + OFF_HB, HB1 = HB0 + 32768u, HB2 = HB0 + 65536u;

    const int zoff = ks * 128 + bq;   // float4 offset within a chunk buffer
    const float4* xz = (const float4*)(smem + OFF_XBUF) + zoff;
    const float4* hz0 = (const float4*)(smem + OFF_HB) + zoff;
    const float4* hz1 = (const float4*)(smem + OFF_HB + 32768) + zoff;
    const float4* hz2 = (const float4*)(smem + OFF_HB + 65536) + zoff;
    // weight pointers per chunk c: base (c*128 + ks*8)*4 + j
    const float4* wv0 = wio + (size_t)(0 * 128 + ks * 8) * 4 + j;
    const float2* wc0 = wcc + (size_t)(0 * 128 + ks * 8) * 4 + j;
    const float4* wv1 = wio + (size_t)(1 * 128 + ks * 8) * 4 + j;
    const float2* wc1 = wcc + (size_t)(1 * 128 + ks * 8) * 4 + j;
    const float4* wv2 = wio + (size_t)(2 * 128 + ks * 8) * 4 + j;
    const float2* wc2p = wcc + (size_t)(2 * 128 + ks * 8) * 4 + j;
    const float4* wv3 = wio + (size_t)(3 * 128 + ks * 8) * 4 + j;
    const float2* wc3 = wcc + (size_t)(3 * 128 + ks * 8) * 4 + j;
    const float4* wv4 = wio + (size_t)(4 * 128 + ks * 8) * 4 + j;
    const float2* wc4 = wcc + (size_t)(4 * 128 + ks * 8) * 4 + j;

    Acc A;
    acc_zero(A);

    // prologue: x(0) -> xbuf, compute x-part(0); commit hc1..3 from zeros
    commit_chunk(XB, g_xT, tid);
    CP_WAIT(0);
    __syncthreads();
    gemm_part(xz, wv0, wc0, A, 0, 8);
    commit_chunk(HB0, g_zero, tid);
    commit_chunk(HB1, g_zero + 8192, tid);
    commit_chunk(HB2, g_zero + 16384, tid);

    for (int t = 0; t < T_STEPS; ++t) {
        const float* hsrc = (t == 0) ? g_zero : (g_HallT + (size_t)(t - 1) * 32768);
        const bool nl = (t < T_STEPS - 1);

        // h chunk 1
        CP_WAIT(2);
        __syncthreads();
        gemm_part(hz0, wv1, wc1, A, 0, 8);
        __syncthreads();                         // HB0 free
        commit_chunk(HB0, hsrc + 24576, tid);    // hc4
        if (nl) commit_chunk(XB, g_xT + (size_t)(t + 1) * 8192, tid);

        // h chunk 2
        if (nl) { CP_WAIT(3); } else { CP_WAIT(2); }
        __syncthreads();
        gemm_part(hz1, wv2, wc2p, A, 0, 8);

        // h chunk 3
        if (nl) { CP_WAIT(2); } else { CP_WAIT(1); }
        __syncthreads();
        gemm_part(hz2, wv3, wc3, A, 0, 8);

        // h chunk 4
        if (nl) { CP_WAIT(1); } else { CP_WAIT(0); }
        __syncthreads();
        gemm_part(hz0, wv4, wc4, A, 0, 8);

        CP_WAIT(0);          // x(t+1) landed (no-op at t=511)
        __syncthreads();     // all computes done; red (aliases HB) safe; xbuf visible

        // spill 12 partials, stride 13 f32x2 (bank-safe)
        {
            float2* mr = red + (size_t)tid * 13;
#pragma unroll
            for (int g = 0; g < 3; ++g)
#pragma unroll
                for (int p = 0; p < 4; ++p) mr[g * 4 + p] = A.a[g][p];
        }
        __syncthreads();

        if (tid < 128) {  // tail: warps 0-3
            const int w = tid >> 5, l = tid & 31;
            const int bqt = (l & 15) >> 1;
            const int slot = (l & 1) + ((l >> 4) << 1);
            float2 pi = make_float2(bi, bi), po = make_float2(bo, bo), pc = make_float2(bc, bc);
#pragma unroll
            for (int k2 = 0; k2 < 16; ++k2) {
                const float2* r = red + (size_t)((k2 * 4 + w) * 8 + bqt) * 13;
                float2 r0 = r[slot], r1 = r[4 + slot], r2 = r[8 + slot];
                pi.x += r0.x; pi.y += r0.y;
                po.x += r1.x; po.y += r1.y;
                pc.x += r2.x; pc.y += r2.y;
            }
            float2 f0 = make_float2(0.f, 0.f), f1 = f0, f2 = f0, f3 = f0;
#pragma unroll
            for (int lag = 0; lag < KLAG; lag += 4) {
                float w0 = wds[(lag    ) * 4 + w];
                float w1 = wds[(lag + 1) * 4 + w];
                float w2 = wds[(lag + 2) * 4 + w];
                float w3 = wds[(lag + 3) * 4 + w];
                f0 = ffma2(ch[(size_t)(((t + lag    ) & 31) * 4 + w) * 32 + l], make_float2(w0, w0), f0);
                f1 = ffma2(ch[(size_t)(((t + lag + 1) & 31) * 4 + w) * 32 + l], make_float2(w1, w1), f1);
                f2 = ffma2(ch[(size_t)(((t + lag + 2) & 31) * 4 + w) * 32 + l], make_float2(w2, w2), f2);
                f3 = ffma2(ch[(size_t)(((t + lag + 3) & 31) * 4 + w) * 32 + l], make_float2(w3, w3), f3);
            }
            float2 frac = make_float2((f0.x + f1.x) + (f2.x + f3.x),
                                      (f0.y + f1.y) + (f2.y + f3.y));
            float2 ig = make_float2(sigf(pi.x), sigf(pi.y));
            float2 og = make_float2(sigf(po.x), sigf(po.y));
            float2 gg = make_float2(tanh_f(pc.x), tanh_f(pc.y));
            float2 c2 = make_float2(ig.x * gg.x - frac.x, ig.y * gg.y - frac.y);
            ch[(size_t)((t & 31) * 4 + w) * 32 + l] = c2;
            float2 h2 = make_float2(og.x * tanh_f(c2.x), og.y * tanh_f(c2.y));

            int nh = nhb + w;
            *(float2*)&g_HallT[(size_t)t * 32768 + (size_t)nh * 64 + 2 * l] = h2;
            if (t == T_STEPS - 1) {
                d_out[OUT_HLAST + (size_t)(2 * l) * H_N + nh]     = h2.x;
                d_out[OUT_HLAST + (size_t)(2 * l + 1) * H_N + nh] = h2.y;
            }
            asm volatile("bar.sync 1, 128;" ::: "memory");
            if (tid == 0) flag_store(&g_flags[blockIdx.x * 32], (unsigned)(t + 1));
        }

        if (nl) {
            acc_zero(A);
            gemm_part(xz, wv0, wc0, A, 0, 4);     // x-part(t+1), first half
            if (tid >= 128 && tid < 256) {        // pollers: warps 4-7
                unsigned tgt = (unsigned)(t + 1);
                while (flag_load(&g_flags[(tid - 128) * 32]) < tgt) { }
            }
            __syncthreads();
            const float* hn = g_HallT + (size_t)t * 32768;
            commit_chunk(HB0, hn, tid);
            commit_chunk(HB1, hn + 8192, tid);
            commit_chunk(HB2, hn + 16384, tid);
            gemm_part(xz, wv0, wc0, A, 4, 8);     // x-part(t+1), second half
        }
    }

    __syncthreads();
    // dump hc_last: slot l == lag l (512 % 32 == 0)
    const float* chf = (const float*)ch;
    for (int idx = tid; idx < KLAG * B_N * 4; idx += NTHR) {
        int l = idx >> 8;
        int rem = idx & 255;
        int b = rem >> 2;
        int jj = rem & 3;
        float v = chf[((size_t)(l * 4 + jj) * 32 + (b >> 1)) * 2 + (b & 1)];
        d_out[OUT_HC + (size_t)l * (B_N * H_N) + (size_t)b * H_N + nhb + jj] = v;
    }
}

// ---------------- output projection ----------------
__global__ void __launch_bounds__(256) proj_kernel(
    const float* __restrict__ W_out, const float* __restrict__ b_out,
    float* __restrict__ out)
{
    __shared__ float At[32 * 64];
    __shared__ float Wt[32 * 128];
    int t = blockIdx.x;
    int tid = threadIdx.x;
    int tx = tid & 15, ty = tid >> 4;

    float2 acc[4][4];
#pragma unroll
    for (int a = 0; a < 4; ++a)
#pragma unroll
        for (int p = 0; p < 4; ++p) acc[a][p] = make_float2(0.f, 0.f);

    const float* Asrc = g_HallT + (size_t)t * H_N * B_N;
    for (int c = 0; c < 16; ++c) {
        __syncthreads();
        {
            float4* At4 = (float4*)At;
            const float4* s4 = (const float4*)(Asrc + (size_t)c * 2048);
            for (int i = tid; i < 512; i += 256) At4[i] = s4[i];
            float4* Wt4 = (float4*)Wt;
            const float4* w4 = (const float4*)(W_out + (size_t)c * 32 * 128);
            for (int i = tid; i < 1024; i += 256) Wt4[i] = w4[i];
        }
        __syncthreads();
        const float4* av = (const float4*)At + ty;
        const float2* wv = (const float2*)Wt + tx;
#pragma unroll 4
        for (int k = 0; k < 32; ++k) {
            float4 a4 = av[k * 16];
            float2 w[4];
#pragma unroll
            for (int p = 0; p < 4; ++p) w[p] = wv[k * 64 + p * 16];
            float2 ad[4];
            ad[0] = make_float2(a4.x, a4.x);
            ad[1] = make_float2(a4.y, a4.y);
            ad[2] = make_float2(a4.z, a4.z);
            ad[3] = make_float2(a4.w, a4.w);
#pragma unroll
            for (int a = 0; a < 4; ++a)
#pragma unroll
                for (int p = 0; p < 4; ++p)
                    acc[a][p] = ffma2(w[p], ad[a], acc[a][p]);
        }
    }

    float* orow = out + (size_t)t * B_N * O_N;
#pragma unroll
    for (int a = 0; a < 4; ++a) {
        int b = ty * 4 + a;
#pragma unroll
        for (int p = 0; p < 4; ++p) {
            int op = tx + p * 16;
            float2 bo2 = *(const float2*)(b_out + 2 * op);
            float2 r = make_float2(acc[a][p].x + bo2.x, acc[a][p].y + bo2.y);
            *(float2*)(orow + (size_t)b * O_N + 2 * op) = r;
        }
    }
}

// ---------------- launch ----------------
extern "C" void kernel_launch(void* const* d_in, const int* in_sizes, int n_in,
                              void* d_out, int out_size)
{
    (void)in_sizes; (void)n_in; (void)out_size;
    const float* x     = (const float*)d_in[0];
    const float* W_i   = (const float*)d_in[1];
    const float* b_i   = (const float*)d_in[2];
    const float* W_o   = (const float*)d_in[3];
    const float* b_o   = (const float*)d_in[4];
    const float* W_c   = (const float*)d_in[5];
    const float* b_c   = (const float*)d_in[6];
    const float* W_out = (const float*)d_in[7];
    const float* b_out = (const float*)d_in[8];
    const float* dv    = (const float*)d_in[9];
    float* out = (float*)d_out;

    cudaFuncSetAttribute(recurrent_kernel,
                         cudaFuncAttributeMaxDynamicSharedMemorySize, SMEM_TOTAL);

    init_kernel<<<16, 512>>>(dv);
    transpose_x<<<T_STEPS, 256>>>(x);
    recurrent_kernel<<<NCTA, NTHR, SMEM_TOTAL>>>(W_i, b_i, W_o, b_o, W_c, b_c, out);
    proj_kernel<<<T_STEPS, 256>>>(W_out, b_out, out);
}